// round 13
// baseline (speedup 1.0000x reference)
#include <cuda_runtime.h>
#include <math.h>

// AdderNet, batch-minor, zero-halo padded intermediates, FFMA-imm inner math:
// d = fma(x, 2.0, -2w); acc = fma(|d|, 0.5, acc)   (rt_SMSP=1 both, exact).
#define B 4096
typedef unsigned long long ull;

__device__ __forceinline__ ull pk2(float a, float b) {
    ull r; asm("mov.b64 %0,{%1,%2};" : "=l"(r) : "f"(a), "f"(b)); return r;
}
__device__ __forceinline__ void AB(float& acc, float v, float wn2) {
    float d = __fmaf_rn(v, 2.0f, wn2);
    acc = __fmaf_rn(fabsf(d), 0.5f, acc);
}

// Padded layouts; halo stays zero forever (globals zero-init, never written).
__device__ float g_a1[16 * 15 * 15 * B];   // [c][y][x][b], interior 1..13
__device__ float g_a2[32 * 9 * 9 * B];     // [o][y][x][b], interior 1..7
__device__ float g_a3[16 * 4 * 4 * B];     // [o][q][b]

// ---------------------------------------------------------------------------
// Layer 1: x[b][784] (-0.5) -> a1p, s2 p0, relu((10-s)/4).
// ---------------------------------------------------------------------------
__global__ __launch_bounds__(256) void k_layer1(const float* __restrict__ x,
                                                const float* __restrict__ w1,
                                                float* __restrict__ a1) {
    extern __shared__ float dyn[];
    float* xs = dyn;                     // [784][18]
    float* wn = dyn + 784 * 18;          // [k*16+o] = -2*w1[o*9+k]

    int t = threadIdx.x;
    int b0 = blockIdx.x * 16;
    if (t < 144) { int o = t / 9, k = t % 9; wn[k * 16 + o] = -2.0f * w1[t]; }
#pragma unroll 1
    for (int img = 0; img < 16; img++) {
        const float* xb = x + (b0 + img) * 784;
        for (int p = t; p < 784; p += 256)
            xs[p * 18 + img] = xb[p] - 0.5f;
    }
    __syncthreads();

    int i2 = t & 7;
    int slot = t >> 3;
    for (int pass = 0; pass < 6; pass++) {
        int pix = pass * 32 + slot;
        if (pix >= 169) break;
        int py = pix / 13, px = pix - py * 13;

        float2 v[9];
#pragma unroll
        for (int kh = 0; kh < 3; kh++)
#pragma unroll
            for (int kw = 0; kw < 3; kw++)
                v[kh * 3 + kw] =
                    *(const float2*)&xs[((py * 2 + kh) * 28 + px * 2 + kw) * 18 + i2 * 2];

        float s0[16], s1[16];
#pragma unroll
        for (int c = 0; c < 16; c++) { s0[c] = 0.0f; s1[c] = 0.0f; }
#pragma unroll
        for (int k = 0; k < 9; k++) {
            const float4* wr = (const float4*)&wn[k * 16];
#pragma unroll
            for (int j4 = 0; j4 < 4; j4++) {
                float4 w = wr[j4];
                AB(s0[j4 * 4 + 0], v[k].x, w.x); AB(s1[j4 * 4 + 0], v[k].y, w.x);
                AB(s0[j4 * 4 + 1], v[k].x, w.y); AB(s1[j4 * 4 + 1], v[k].y, w.y);
                AB(s0[j4 * 4 + 2], v[k].x, w.z); AB(s1[j4 * 4 + 2], v[k].y, w.z);
                AB(s0[j4 * 4 + 3], v[k].x, w.w); AB(s1[j4 * 4 + 3], v[k].y, w.w);
            }
        }

        float* op = a1 + ((py + 1) * 15 + (px + 1)) * B + b0 + i2 * 2;
#pragma unroll
        for (int c = 0; c < 16; c++) {
            float f0 = fmaxf((10.0f - s0[c]) * 0.25f, 0.0f);
            float f1 = fmaxf((10.0f - s1[c]) * 0.25f, 0.0f);
            *(ull*)(op + c * (225 * B)) = pk2(f0, f1);
        }
    }
}

// ---------------------------------------------------------------------------
// Layer 2: a1p -> a2p, s2 p1, relu((130-s)/8).
// Grid (64,7,2), CTA 224 = 7 warps; warp = out-pixel, lane = 2 images.
// ---------------------------------------------------------------------------
__global__ __launch_bounds__(224, 4) void k_layer2(const float* __restrict__ a1,
                                                   const float* __restrict__ w2,
                                                   float* __restrict__ a2) {
    __shared__ __align__(16) float wn[2304];  // [(c*9+k)*16+j] = -2*w2[(ob*16+j)*144+c*9+k]
    int t = threadIdx.x;
    int imgg = blockIdx.x, pixg = blockIdx.y, ob = blockIdx.z;
    for (int i = t; i < 2304; i += 224) {
        int r = i >> 4, j = i & 15;
        wn[i] = -2.0f * w2[(ob * 16 + j) * 144 + r];
    }
    __syncthreads();

    int warp = t >> 5, lane = t & 31;
    int pix = pixg * 7 + warp;
    int py = pix / 7, px = pix - py * 7;
    int b = imgg * 64 + lane * 2;

    const float* base = a1 + ((py * 2) * 15 + px * 2) * B + b;

    float s0[16], s1[16];
#pragma unroll
    for (int j = 0; j < 16; j++) { s0[j] = 0.0f; s1[j] = 0.0f; }

#pragma unroll 1
    for (int c = 0; c < 16; c++) {
        const float* bc = base + c * (225 * B);
        float2 v[9];
#pragma unroll
        for (int kh = 0; kh < 3; kh++)
#pragma unroll
            for (int kw = 0; kw < 3; kw++)
                v[kh * 3 + kw] = *(const float2*)(bc + (kh * 15 + kw) * B);
#pragma unroll
        for (int k = 0; k < 9; k++) {
            const float4* wr = (const float4*)&wn[(c * 9 + k) * 16];
#pragma unroll
            for (int j4 = 0; j4 < 4; j4++) {
                float4 w = wr[j4];
                AB(s0[j4 * 4 + 0], v[k].x, w.x); AB(s1[j4 * 4 + 0], v[k].y, w.x);
                AB(s0[j4 * 4 + 1], v[k].x, w.y); AB(s1[j4 * 4 + 1], v[k].y, w.y);
                AB(s0[j4 * 4 + 2], v[k].x, w.z); AB(s1[j4 * 4 + 2], v[k].y, w.z);
                AB(s0[j4 * 4 + 3], v[k].x, w.w); AB(s1[j4 * 4 + 3], v[k].y, w.w);
            }
        }
    }

    float* op = a2 + ((ob * 16) * 81 + (py + 1) * 9 + (px + 1)) * B + b;
#pragma unroll
    for (int j = 0; j < 16; j++) {
        float f0 = fmaxf((130.0f - s0[j]) * 0.125f, 0.0f);
        float f1 = fmaxf((130.0f - s1[j]) * 0.125f, 0.0f);
        *(ull*)(op + j * (81 * B)) = pk2(f0, f1);
    }
}

// ---------------------------------------------------------------------------
// Layer 3: a2p -> a3, s2 p1, relu((280-s)/16).
// Grid (64,4,2), CTA 128 = 4 warps; warp = out-pixel q, lane = 2 images.
// ---------------------------------------------------------------------------
__global__ __launch_bounds__(128, 6) void k_layer3(const float* __restrict__ a2,
                                                   const float* __restrict__ w3,
                                                   float* __restrict__ a3) {
    __shared__ __align__(16) float wn[2304];  // [(c*9+k)*8+j] = -2*w3[(ob*8+j)*288+c*9+k]
    int t = threadIdx.x;
    int imgg = blockIdx.x, qg = blockIdx.y, ob = blockIdx.z;
    for (int i = t; i < 2304; i += 128) {
        int r = i >> 3, j = i & 7;
        wn[i] = -2.0f * w3[(ob * 8 + j) * 288 + r];
    }
    __syncthreads();

    int warp = t >> 5, lane = t & 31;
    int q = qg * 4 + warp;
    int qy = q >> 2, qx = q & 3;
    int b = imgg * 64 + lane * 2;

    const float* base = a2 + ((qy * 2) * 9 + qx * 2) * B + b;

    float s0[8], s1[8];
#pragma unroll
    for (int j = 0; j < 8; j++) { s0[j] = 0.0f; s1[j] = 0.0f; }

#pragma unroll 1
    for (int c = 0; c < 32; c++) {
        const float* bc = base + c * (81 * B);
        float2 v[9];
#pragma unroll
        for (int kh = 0; kh < 3; kh++)
#pragma unroll
            for (int kw = 0; kw < 3; kw++)
                v[kh * 3 + kw] = *(const float2*)(bc + (kh * 9 + kw) * B);
#pragma unroll
        for (int k = 0; k < 9; k++) {
            const float4* wr = (const float4*)&wn[(c * 9 + k) * 8];
#pragma unroll
            for (int j4 = 0; j4 < 2; j4++) {
                float4 w = wr[j4];
                AB(s0[j4 * 4 + 0], v[k].x, w.x); AB(s1[j4 * 4 + 0], v[k].y, w.x);
                AB(s0[j4 * 4 + 1], v[k].x, w.y); AB(s1[j4 * 4 + 1], v[k].y, w.y);
                AB(s0[j4 * 4 + 2], v[k].x, w.z); AB(s1[j4 * 4 + 2], v[k].y, w.z);
                AB(s0[j4 * 4 + 3], v[k].x, w.w); AB(s1[j4 * 4 + 3], v[k].y, w.w);
            }
        }
    }

    float* op = a3 + ((ob * 8) * 16 + q) * B + b;
#pragma unroll
    for (int j = 0; j < 8; j++) {
        float f0 = fmaxf((280.0f - s0[j]) * 0.0625f, 0.0f);
        float f1 = fmaxf((280.0f - s1[j]) * 0.0625f, 0.0f);
        *(ull*)(op + j * (16 * B)) = pk2(f0, f1);
    }
}

// ---------------------------------------------------------------------------
// Layer 4 + log_softmax, no reduction: CTA 320 = 10 warps; warp = output o,
// lane = one of 32 consecutive images. Each thread builds the FULL logit
// (144 taps: coalesced LDG shared across the 10 warps -> L1-hot, uniform LDS
// weight, 2 FFMA). Logits to smem, warp 0 does per-image softmax.
// ---------------------------------------------------------------------------
__global__ __launch_bounds__(320) void k_layer4(const float* __restrict__ a3,
                                                const float* __restrict__ w4,
                                                float* __restrict__ out) {
    __shared__ float wo[10][144];   // wo[o][c*9+k] = -2*w4[o*144 + c*9+k]
    __shared__ float lg[10][32];
    int t = threadIdx.x;
    for (int i = t; i < 1440; i += 320)
        wo[i / 144][i % 144] = -2.0f * w4[i];
    __syncthreads();

    int lane = t & 31;
    int o = t >> 5;                 // 0..9
    int img0 = blockIdx.x * 32;
    const float* base = a3 + img0 + lane;
    const float* wr = wo[o];

    float acc = 0.0f;
#pragma unroll
    for (int c = 0; c < 16; c++)
#pragma unroll
        for (int kh = 0; kh < 3; kh++)
#pragma unroll
            for (int kw = 0; kw < 3; kw++)
                AB(acc, base[(c * 16 + kh * 4 + kw) * B], wr[c * 9 + kh * 3 + kw]);

    lg[o][lane] = acc;
    __syncthreads();

    if (t < 32) {
        float l[10];
#pragma unroll
        for (int oo = 0; oo < 10; oo++) l[oo] = -lg[oo][t];
        float m = l[0];
#pragma unroll
        for (int oo = 1; oo < 10; oo++) m = fmaxf(m, l[oo]);
        float e = 0.0f;
#pragma unroll
        for (int oo = 0; oo < 10; oo++) e += expf(l[oo] - m);
        float d = m + logf(e);

        ull* op = (ull*)(out + (img0 + t) * 10);
#pragma unroll
        for (int o2 = 0; o2 < 5; o2++)
            op[o2] = pk2(l[2 * o2] - d, l[2 * o2 + 1] - d);
    }
}

// ---------------------------------------------------------------------------
extern "C" void kernel_launch(void* const* d_in, const int* in_sizes, int n_in,
                              void* d_out, int out_size) {
    const float* x  = (const float*)d_in[0];
    const float* w1 = (const float*)d_in[1];
    const float* w2 = (const float*)d_in[2];
    const float* w3 = (const float*)d_in[3];
    const float* w4 = (const float*)d_in[4];
    float* out = (float*)d_out;

    float *a1, *a2, *a3;
    cudaGetSymbolAddress((void**)&a1, g_a1);
    cudaGetSymbolAddress((void**)&a2, g_a2);
    cudaGetSymbolAddress((void**)&a3, g_a3);

    const int smem1 = 784 * 18 * 4 + 144 * 4;   // 57024 B
    cudaFuncSetAttribute(k_layer1, cudaFuncAttributeMaxDynamicSharedMemorySize,
                         smem1);

    k_layer1<<<B / 16, 256, smem1>>>(x, w1, a1);
    k_layer2<<<dim3(64, 7, 2), 224>>>(a1, w2, a2);
    k_layer3<<<dim3(64, 4, 2), 128>>>(a2, w3, a3);
    k_layer4<<<B / 32, 320>>>(a3, w4, out);
}

// round 14
// speedup vs baseline: 1.1303x; 1.1303x over previous
#include <cuda_runtime.h>
#include <math.h>

// AdderNet, batch-minor, zero-halo padded intermediates, FFMA-imm inner math:
// d = fma(x, 2.0, -2w); acc = fma(|d|, 0.5, acc)   (rt_SMSP=1 both, exact).
#define B 4096
typedef unsigned long long ull;

__device__ __forceinline__ ull pk2(float a, float b) {
    ull r; asm("mov.b64 %0,{%1,%2};" : "=l"(r) : "f"(a), "f"(b)); return r;
}
__device__ __forceinline__ void AB(float& acc, float v, float wn2) {
    float d = __fmaf_rn(v, 2.0f, wn2);
    acc = __fmaf_rn(fabsf(d), 0.5f, acc);
}

// Padded layouts; halo stays zero forever (globals zero-init, never written).
__device__ float g_a1[16 * 15 * 15 * B];   // [c][y][x][b], interior 1..13
__device__ float g_a2[32 * 9 * 9 * B];     // [o][y][x][b], interior 1..7
__device__ float g_a3[16 * 4 * 4 * B];     // [o][q][b]

// ---------------------------------------------------------------------------
// Layer 1: x[b][784] (-0.5) -> a1p, s2 p0, relu((10-s)/4).
// ---------------------------------------------------------------------------
__global__ __launch_bounds__(256) void k_layer1(const float* __restrict__ x,
                                                const float* __restrict__ w1,
                                                float* __restrict__ a1) {
    extern __shared__ float dyn[];
    float* xs = dyn;                     // [784][18]
    float* wn = dyn + 784 * 18;          // [k*16+o] = -2*w1[o*9+k]

    int t = threadIdx.x;
    int b0 = blockIdx.x * 16;
    if (t < 144) { int o = t / 9, k = t % 9; wn[k * 16 + o] = -2.0f * w1[t]; }
    for (int i = t; i < 784 * 16; i += 256) {
        int img = i / 784, p = i - img * 784;
        xs[p * 18 + img] = x[(b0 + img) * 784 + p] - 0.5f;
    }
    __syncthreads();

    int i2 = t & 7;
    int slot = t >> 3;
    for (int pass = 0; pass < 6; pass++) {
        int pix = pass * 32 + slot;
        if (pix >= 169) break;
        int py = pix / 13, px = pix - py * 13;

        float2 v[9];
#pragma unroll
        for (int kh = 0; kh < 3; kh++)
#pragma unroll
            for (int kw = 0; kw < 3; kw++)
                v[kh * 3 + kw] =
                    *(const float2*)&xs[((py * 2 + kh) * 28 + px * 2 + kw) * 18 + i2 * 2];

        float s0[16], s1[16];
#pragma unroll
        for (int c = 0; c < 16; c++) { s0[c] = 0.0f; s1[c] = 0.0f; }
#pragma unroll
        for (int k = 0; k < 9; k++) {
            const float4* wr = (const float4*)&wn[k * 16];
#pragma unroll
            for (int j4 = 0; j4 < 4; j4++) {
                float4 w = wr[j4];
                AB(s0[j4 * 4 + 0], v[k].x, w.x); AB(s1[j4 * 4 + 0], v[k].y, w.x);
                AB(s0[j4 * 4 + 1], v[k].x, w.y); AB(s1[j4 * 4 + 1], v[k].y, w.y);
                AB(s0[j4 * 4 + 2], v[k].x, w.z); AB(s1[j4 * 4 + 2], v[k].y, w.z);
                AB(s0[j4 * 4 + 3], v[k].x, w.w); AB(s1[j4 * 4 + 3], v[k].y, w.w);
            }
        }

        float* op = a1 + ((py + 1) * 15 + (px + 1)) * B + b0 + i2 * 2;
#pragma unroll
        for (int c = 0; c < 16; c++) {
            float f0 = fmaxf((10.0f - s0[c]) * 0.25f, 0.0f);
            float f1 = fmaxf((10.0f - s1[c]) * 0.25f, 0.0f);
            *(ull*)(op + c * (225 * B)) = pk2(f0, f1);
        }
    }
}

// ---------------------------------------------------------------------------
// Layer 2: a1p -> a2p, s2 p1, relu((130-s)/8).
// Grid (64,7,2), CTA 224 = 7 warps; warp = out-pixel, lane = 2 images.
// NOTE: occ 3 is the sweet spot; occ 4 caps regs at 73 and spills (R13).
// ---------------------------------------------------------------------------
__global__ __launch_bounds__(224, 3) void k_layer2(const float* __restrict__ a1,
                                                   const float* __restrict__ w2,
                                                   float* __restrict__ a2) {
    __shared__ __align__(16) float wn[2304];  // [(c*9+k)*16+j] = -2*w2[(ob*16+j)*144+c*9+k]
    int t = threadIdx.x;
    int imgg = blockIdx.x, pixg = blockIdx.y, ob = blockIdx.z;
    for (int i = t; i < 2304; i += 224) {
        int r = i >> 4, j = i & 15;
        wn[i] = -2.0f * w2[(ob * 16 + j) * 144 + r];
    }
    __syncthreads();

    int warp = t >> 5, lane = t & 31;
    int pix = pixg * 7 + warp;
    int py = pix / 7, px = pix - py * 7;
    int b = imgg * 64 + lane * 2;

    const float* base = a1 + ((py * 2) * 15 + px * 2) * B + b;

    float s0[16], s1[16];
#pragma unroll
    for (int j = 0; j < 16; j++) { s0[j] = 0.0f; s1[j] = 0.0f; }

#pragma unroll 1
    for (int c = 0; c < 16; c++) {
        const float* bc = base + c * (225 * B);
        float2 v[9];
#pragma unroll
        for (int kh = 0; kh < 3; kh++)
#pragma unroll
            for (int kw = 0; kw < 3; kw++)
                v[kh * 3 + kw] = *(const float2*)(bc + (kh * 15 + kw) * B);
#pragma unroll
        for (int k = 0; k < 9; k++) {
            const float4* wr = (const float4*)&wn[(c * 9 + k) * 16];
#pragma unroll
            for (int j4 = 0; j4 < 4; j4++) {
                float4 w = wr[j4];
                AB(s0[j4 * 4 + 0], v[k].x, w.x); AB(s1[j4 * 4 + 0], v[k].y, w.x);
                AB(s0[j4 * 4 + 1], v[k].x, w.y); AB(s1[j4 * 4 + 1], v[k].y, w.y);
                AB(s0[j4 * 4 + 2], v[k].x, w.z); AB(s1[j4 * 4 + 2], v[k].y, w.z);
                AB(s0[j4 * 4 + 3], v[k].x, w.w); AB(s1[j4 * 4 + 3], v[k].y, w.w);
            }
        }
    }

    float* op = a2 + ((ob * 16) * 81 + (py + 1) * 9 + (px + 1)) * B + b;
#pragma unroll
    for (int j = 0; j < 16; j++) {
        float f0 = fmaxf((130.0f - s0[j]) * 0.125f, 0.0f);
        float f1 = fmaxf((130.0f - s1[j]) * 0.125f, 0.0f);
        *(ull*)(op + j * (81 * B)) = pk2(f0, f1);
    }
}

// ---------------------------------------------------------------------------
// Layer 3: a2p -> a3, s2 p1, relu((280-s)/16).
// Grid (64,4,2), CTA 128 = 4 warps; warp = out-pixel q, lane = 2 images.
// ---------------------------------------------------------------------------
__global__ __launch_bounds__(128, 6) void k_layer3(const float* __restrict__ a2,
                                                   const float* __restrict__ w3,
                                                   float* __restrict__ a3) {
    __shared__ __align__(16) float wn[2304];  // [(c*9+k)*8+j] = -2*w3[(ob*8+j)*288+c*9+k]
    int t = threadIdx.x;
    int imgg = blockIdx.x, qg = blockIdx.y, ob = blockIdx.z;
    for (int i = t; i < 2304; i += 128) {
        int r = i >> 3, j = i & 7;
        wn[i] = -2.0f * w3[(ob * 8 + j) * 288 + r];
    }
    __syncthreads();

    int warp = t >> 5, lane = t & 31;
    int q = qg * 4 + warp;
    int qy = q >> 2, qx = q & 3;
    int b = imgg * 64 + lane * 2;

    const float* base = a2 + ((qy * 2) * 9 + qx * 2) * B + b;

    float s0[8], s1[8];
#pragma unroll
    for (int j = 0; j < 8; j++) { s0[j] = 0.0f; s1[j] = 0.0f; }

#pragma unroll 1
    for (int c = 0; c < 32; c++) {
        const float* bc = base + c * (81 * B);
        float2 v[9];
#pragma unroll
        for (int kh = 0; kh < 3; kh++)
#pragma unroll
            for (int kw = 0; kw < 3; kw++)
                v[kh * 3 + kw] = *(const float2*)(bc + (kh * 9 + kw) * B);
#pragma unroll
        for (int k = 0; k < 9; k++) {
            const float4* wr = (const float4*)&wn[(c * 9 + k) * 8];
#pragma unroll
            for (int j4 = 0; j4 < 2; j4++) {
                float4 w = wr[j4];
                AB(s0[j4 * 4 + 0], v[k].x, w.x); AB(s1[j4 * 4 + 0], v[k].y, w.x);
                AB(s0[j4 * 4 + 1], v[k].x, w.y); AB(s1[j4 * 4 + 1], v[k].y, w.y);
                AB(s0[j4 * 4 + 2], v[k].x, w.z); AB(s1[j4 * 4 + 2], v[k].y, w.z);
                AB(s0[j4 * 4 + 3], v[k].x, w.w); AB(s1[j4 * 4 + 3], v[k].y, w.w);
            }
        }
    }

    float* op = a3 + ((ob * 8) * 16 + q) * B + b;
#pragma unroll
    for (int j = 0; j < 8; j++) {
        float f0 = fmaxf((280.0f - s0[j]) * 0.0625f, 0.0f);
        float f1 = fmaxf((280.0f - s1[j]) * 0.0625f, 0.0f);
        *(ull*)(op + j * (16 * B)) = pk2(f0, f1);
    }
}

// ---------------------------------------------------------------------------
// Layer 4 + log_softmax: CTA 256 = 16 images x 16 channels (t&15 = image ->
// 64B-coalesced LDGs; t>>4 = channel). Grid 256 CTAs (> 148 SMs, balanced).
// Cross-channel reduce in smem, 16-thread softmax tail.
// ---------------------------------------------------------------------------
__global__ __launch_bounds__(256) void k_layer4(const float* __restrict__ a3,
                                                const float* __restrict__ w4,
                                                float* __restrict__ out) {
    __shared__ float wn[1440];         // [(c*9+k)*10+o] = -2*w4[o*144+c*9+k]
    __shared__ float red[16][16][10];  // [channel][img][o]
    int t = threadIdx.x;
    for (int i = t; i < 1440; i += 256) {
        int r = i / 10, o = i - r * 10;
        wn[i] = -2.0f * w4[o * 144 + r];
    }
    __syncthreads();

    int islot = t & 15;
    int c = t >> 4;                    // 0..15
    int img0 = blockIdx.x * 16;

    float acc[10];
#pragma unroll
    for (int o = 0; o < 10; o++) acc[o] = 0.0f;

    const float* base = a3 + img0 + islot;
#pragma unroll
    for (int kh = 0; kh < 3; kh++)
#pragma unroll
        for (int kw = 0; kw < 3; kw++) {
            float v = base[(c * 16 + kh * 4 + kw) * B];   // 64B segment / half-warp
            const float* wr = &wn[(c * 9 + kh * 3 + kw) * 10];
#pragma unroll
            for (int o = 0; o < 10; o++)
                AB(acc[o], v, wr[o]);
        }
#pragma unroll
    for (int o = 0; o < 10; o++) red[c][islot][o] = acc[o];
    __syncthreads();

    if (t < 16) {
        float l[10];
#pragma unroll
        for (int o = 0; o < 10; o++) {
            float s = 0.0f;
#pragma unroll
            for (int cc = 0; cc < 16; cc++) s += red[cc][t][o];
            l[o] = -s;
        }
        float m = l[0];
#pragma unroll
        for (int o = 1; o < 10; o++) m = fmaxf(m, l[o]);
        float e = 0.0f;
#pragma unroll
        for (int o = 0; o < 10; o++) e += expf(l[o] - m);
        float d = m + logf(e);

        ull* op = (ull*)(out + (img0 + t) * 10);
#pragma unroll
        for (int o2 = 0; o2 < 5; o2++)
            op[o2] = pk2(l[2 * o2] - d, l[2 * o2 + 1] - d);
    }
}

// ---------------------------------------------------------------------------
extern "C" void kernel_launch(void* const* d_in, const int* in_sizes, int n_in,
                              void* d_out, int out_size) {
    const float* x  = (const float*)d_in[0];
    const float* w1 = (const float*)d_in[1];
    const float* w2 = (const float*)d_in[2];
    const float* w3 = (const float*)d_in[3];
    const float* w4 = (const float*)d_in[4];
    float* out = (float*)d_out;

    float *a1, *a2, *a3;
    cudaGetSymbolAddress((void**)&a1, g_a1);
    cudaGetSymbolAddress((void**)&a2, g_a2);
    cudaGetSymbolAddress((void**)&a3, g_a3);

    const int smem1 = 784 * 18 * 4 + 144 * 4;   // 57024 B
    cudaFuncSetAttribute(k_layer1, cudaFuncAttributeMaxDynamicSharedMemorySize,
                         smem1);

    k_layer1<<<B / 16, 256, smem1>>>(x, w1, a1);
    k_layer2<<<dim3(64, 7, 2), 224>>>(a1, w2, a2);
    k_layer3<<<dim3(64, 4, 2), 128>>>(a2, w3, a3);
    k_layer4<<<B / 16, 256>>>(a3, w4, out);
}

// round 17
// speedup vs baseline: 1.1498x; 1.0173x over previous
#include <cuda_runtime.h>
#include <math.h>

// AdderNet, batch-minor, zero-halo padded intermediates, FFMA-imm inner math:
// d = fma(x, 2.0, -2w); acc = fma(|d|, 0.5, acc)   (rt_SMSP=1 both, exact).
#define B 4096
typedef unsigned long long ull;

__device__ __forceinline__ ull pk2(float a, float b) {
    ull r; asm("mov.b64 %0,{%1,%2};" : "=l"(r) : "f"(a), "f"(b)); return r;
}
__device__ __forceinline__ void AB(float& acc, float v, float wn2) {
    float d = __fmaf_rn(v, 2.0f, wn2);
    acc = __fmaf_rn(fabsf(d), 0.5f, acc);
}

// Padded layouts; halo stays zero forever (globals zero-init, never written).
__device__ float g_a1[16 * 15 * 15 * B];   // [c][y][x][b], interior 1..13
__device__ float g_a2[32 * 9 * 9 * B];     // [o][y][x][b], interior 1..7
__device__ float g_a3[16 * 4 * 4 * B];     // [o][q][b]

// ---------------------------------------------------------------------------
// Layer 1: x[b][784] -> a1p, s2 p0, relu((10-s)/4).
// The network's input shift (x-0.5) is folded into the weights:
// |(x-0.5) - w| = |x - (w+0.5)|, so wn = -2*(w+0.5) and staging copies x raw.
// ---------------------------------------------------------------------------
__global__ __launch_bounds__(256) void k_layer1(const float* __restrict__ x,
                                                const float* __restrict__ w1,
                                                float* __restrict__ a1) {
    extern __shared__ float dyn[];
    float* xs = dyn;                     // [784][18]
    float* wn = dyn + 784 * 18;          // [k*16+o] = -2*(w1[o*9+k]+0.5)

    int t = threadIdx.x;
    int b0 = blockIdx.x * 16;
    if (t < 144) { int o = t / 9, k = t % 9; wn[k * 16 + o] = -2.0f * (w1[t] + 0.5f); }
    for (int i = t; i < 784 * 16; i += 256) {
        int img = i / 784, p = i - img * 784;
        xs[p * 18 + img] = x[(b0 + img) * 784 + p];
    }
    __syncthreads();

    int i2 = t & 7;
    int slot = t >> 3;
    for (int pass = 0; pass < 6; pass++) {
        int pix = pass * 32 + slot;
        if (pix >= 169) break;
        int py = pix / 13, px = pix - py * 13;

        float2 v[9];
#pragma unroll
        for (int kh = 0; kh < 3; kh++)
#pragma unroll
            for (int kw = 0; kw < 3; kw++)
                v[kh * 3 + kw] =
                    *(const float2*)&xs[((py * 2 + kh) * 28 + px * 2 + kw) * 18 + i2 * 2];

        float s0[16], s1[16];
#pragma unroll
        for (int c = 0; c < 16; c++) { s0[c] = 0.0f; s1[c] = 0.0f; }
#pragma unroll
        for (int k = 0; k < 9; k++) {
            const float4* wr = (const float4*)&wn[k * 16];
#pragma unroll
            for (int j4 = 0; j4 < 4; j4++) {
                float4 w = wr[j4];
                AB(s0[j4 * 4 + 0], v[k].x, w.x); AB(s1[j4 * 4 + 0], v[k].y, w.x);
                AB(s0[j4 * 4 + 1], v[k].x, w.y); AB(s1[j4 * 4 + 1], v[k].y, w.y);
                AB(s0[j4 * 4 + 2], v[k].x, w.z); AB(s1[j4 * 4 + 2], v[k].y, w.z);
                AB(s0[j4 * 4 + 3], v[k].x, w.w); AB(s1[j4 * 4 + 3], v[k].y, w.w);
            }
        }

        float* op = a1 + ((py + 1) * 15 + (px + 1)) * B + b0 + i2 * 2;
#pragma unroll
        for (int c = 0; c < 16; c++) {
            float f0 = fmaxf((10.0f - s0[c]) * 0.25f, 0.0f);
            float f1 = fmaxf((10.0f - s1[c]) * 0.25f, 0.0f);
            *(ull*)(op + c * (225 * B)) = pk2(f0, f1);
        }
    }
}

// ---------------------------------------------------------------------------
// Layer 2: a1p -> a2p, s2 p1, relu((130-s)/8).
// Grid (64,7,2), CTA 224 = 7 warps; warp = out-pixel, lane = 2 images.
// occ 3 is the sweet spot; occ 4 caps regs at 73 and spills (R13 evidence).
// ---------------------------------------------------------------------------
__global__ __launch_bounds__(224, 3) void k_layer2(const float* __restrict__ a1,
                                                   const float* __restrict__ w2,
                                                   float* __restrict__ a2) {
    __shared__ __align__(16) float wn[2304];  // [(c*9+k)*16+j] = -2*w2[(ob*16+j)*144+c*9+k]
    int t = threadIdx.x;
    int imgg = blockIdx.x, pixg = blockIdx.y, ob = blockIdx.z;
    for (int i = t; i < 2304; i += 224) {
        int r = i >> 4, j = i & 15;
        wn[i] = -2.0f * w2[(ob * 16 + j) * 144 + r];
    }
    __syncthreads();

    int warp = t >> 5, lane = t & 31;
    int pix = pixg * 7 + warp;
    int py = pix / 7, px = pix - py * 7;
    int b = imgg * 64 + lane * 2;

    const float* base = a1 + ((py * 2) * 15 + px * 2) * B + b;

    float s0[16], s1[16];
#pragma unroll
    for (int j = 0; j < 16; j++) { s0[j] = 0.0f; s1[j] = 0.0f; }

#pragma unroll 1
    for (int c = 0; c < 16; c++) {
        const float* bc = base + c * (225 * B);
        float2 v[9];
#pragma unroll
        for (int kh = 0; kh < 3; kh++)
#pragma unroll
            for (int kw = 0; kw < 3; kw++)
                v[kh * 3 + kw] = *(const float2*)(bc + (kh * 15 + kw) * B);
#pragma unroll
        for (int k = 0; k < 9; k++) {
            const float4* wr = (const float4*)&wn[(c * 9 + k) * 16];
#pragma unroll
            for (int j4 = 0; j4 < 4; j4++) {
                float4 w = wr[j4];
                AB(s0[j4 * 4 + 0], v[k].x, w.x); AB(s1[j4 * 4 + 0], v[k].y, w.x);
                AB(s0[j4 * 4 + 1], v[k].x, w.y); AB(s1[j4 * 4 + 1], v[k].y, w.y);
                AB(s0[j4 * 4 + 2], v[k].x, w.z); AB(s1[j4 * 4 + 2], v[k].y, w.z);
                AB(s0[j4 * 4 + 3], v[k].x, w.w); AB(s1[j4 * 4 + 3], v[k].y, w.w);
            }
        }
    }

    float* op = a2 + ((ob * 16) * 81 + (py + 1) * 9 + (px + 1)) * B + b;
#pragma unroll
    for (int j = 0; j < 16; j++) {
        float f0 = fmaxf((130.0f - s0[j]) * 0.125f, 0.0f);
        float f1 = fmaxf((130.0f - s1[j]) * 0.125f, 0.0f);
        *(ull*)(op + j * (81 * B)) = pk2(f0, f1);
    }
}

// ---------------------------------------------------------------------------
// Layer 3: a2p -> a3, s2 p1, relu((280-s)/16).
// Grid (64,4,2), CTA 128 = 4 warps; warp = out-pixel q, lane = 2 images.
// ---------------------------------------------------------------------------
__global__ __launch_bounds__(128, 6) void k_layer3(const float* __restrict__ a2,
                                                   const float* __restrict__ w3,
                                                   float* __restrict__ a3) {
    __shared__ __align__(16) float wn[2304];  // [(c*9+k)*8+j] = -2*w3[(ob*8+j)*288+c*9+k]
    int t = threadIdx.x;
    int imgg = blockIdx.x, qg = blockIdx.y, ob = blockIdx.z;
    for (int i = t; i < 2304; i += 128) {
        int r = i >> 3, j = i & 7;
        wn[i] = -2.0f * w3[(ob * 8 + j) * 288 + r];
    }
    __syncthreads();

    int warp = t >> 5, lane = t & 31;
    int q = qg * 4 + warp;
    int qy = q >> 2, qx = q & 3;
    int b = imgg * 64 + lane * 2;

    const float* base = a2 + ((qy * 2) * 9 + qx * 2) * B + b;

    float s0[8], s1[8];
#pragma unroll
    for (int j = 0; j < 8; j++) { s0[j] = 0.0f; s1[j] = 0.0f; }

#pragma unroll 1
    for (int c = 0; c < 32; c++) {
        const float* bc = base + c * (81 * B);
        float2 v[9];
#pragma unroll
        for (int kh = 0; kh < 3; kh++)
#pragma unroll
            for (int kw = 0; kw < 3; kw++)
                v[kh * 3 + kw] = *(const float2*)(bc + (kh * 9 + kw) * B);
#pragma unroll
        for (int k = 0; k < 9; k++) {
            const float4* wr = (const float4*)&wn[(c * 9 + k) * 8];
#pragma unroll
            for (int j4 = 0; j4 < 2; j4++) {
                float4 w = wr[j4];
                AB(s0[j4 * 4 + 0], v[k].x, w.x); AB(s1[j4 * 4 + 0], v[k].y, w.x);
                AB(s0[j4 * 4 + 1], v[k].x, w.y); AB(s1[j4 * 4 + 1], v[k].y, w.y);
                AB(s0[j4 * 4 + 2], v[k].x, w.z); AB(s1[j4 * 4 + 2], v[k].y, w.z);
                AB(s0[j4 * 4 + 3], v[k].x, w.w); AB(s1[j4 * 4 + 3], v[k].y, w.w);
            }
        }
    }

    float* op = a3 + ((ob * 8) * 16 + q) * B + b;
#pragma unroll
    for (int j = 0; j < 8; j++) {
        float f0 = fmaxf((280.0f - s0[j]) * 0.0625f, 0.0f);
        float f1 = fmaxf((280.0f - s1[j]) * 0.0625f, 0.0f);
        *(ull*)(op + j * (16 * B)) = pk2(f0, f1);
    }
}

// ---------------------------------------------------------------------------
// Layer 4 + log_softmax: grid 256 x block 512.
// Thread = (img-slot t&15, channel (t>>4)&15, kh-part t>>8):
//   part 0 -> kh in {0,1}; part 1 -> kh = 2.
// 256 CTAs (>148 SMs), 27 warps/SM. Partials in smem red[32][16][10];
// 160 threads sum per-(img,o); 16 threads finish softmax.
// ---------------------------------------------------------------------------
__global__ __launch_bounds__(512) void k_layer4(const float* __restrict__ a3,
                                                const float* __restrict__ w4,
                                                float* __restrict__ out) {
    __shared__ float wn[1440];         // [(c*9+k)*10+o] = -2*w4[o*144+c*9+k]
    __shared__ float red[32][16][10];  // [(c,part)][img][o]
    __shared__ float lg[16][10];
    int t = threadIdx.x;
    for (int i = t; i < 1440; i += 512) {
        int r = i / 10, o = i - r * 10;
        wn[i] = -2.0f * w4[o * 144 + r];
    }
    __syncthreads();

    int islot = t & 15;
    int rest = t >> 4;                 // 0..31
    int c = rest & 15;
    int part = rest >> 4;              // 0 or 1
    int img0 = blockIdx.x * 16;

    float acc[10];
#pragma unroll
    for (int o = 0; o < 10; o++) acc[o] = 0.0f;

    const float* base = a3 + img0 + islot;
    if (part == 0) {
#pragma unroll
        for (int kh = 0; kh < 2; kh++)
#pragma unroll
            for (int kw = 0; kw < 3; kw++) {
                float v = base[(c * 16 + kh * 4 + kw) * B];
                const float* wr = &wn[(c * 9 + kh * 3 + kw) * 10];
#pragma unroll
                for (int o = 0; o < 10; o++) AB(acc[o], v, wr[o]);
            }
    } else {
#pragma unroll
        for (int kw = 0; kw < 3; kw++) {
            float v = base[(c * 16 + 2 * 4 + kw) * B];
            const float* wr = &wn[(c * 9 + 2 * 3 + kw) * 10];
#pragma unroll
            for (int o = 0; o < 10; o++) AB(acc[o], v, wr[o]);
        }
    }
#pragma unroll
    for (int o = 0; o < 10; o++) red[rest][islot][o] = acc[o];
    __syncthreads();

    if (t < 160) {
        int img = t & 15, o = t >> 4;   // o in 0..9
        float s = 0.0f;
#pragma unroll
        for (int r = 0; r < 32; r++) s += red[r][img][o];
        lg[img][o] = s;
    }
    __syncthreads();

    if (t < 16) {
        float l[10];
#pragma unroll
        for (int o = 0; o < 10; o++) l[o] = -lg[t][o];
        float m = l[0];
#pragma unroll
        for (int o = 1; o < 10; o++) m = fmaxf(m, l[o]);
        float e = 0.0f;
#pragma unroll
        for (int o = 0; o < 10; o++) e += expf(l[o] - m);
        float d = m + logf(e);

        ull* op = (ull*)(out + (img0 + t) * 10);
#pragma unroll
        for (int o2 = 0; o2 < 5; o2++)
            op[o2] = pk2(l[2 * o2] - d, l[2 * o2 + 1] - d);
    }
}

// ---------------------------------------------------------------------------
extern "C" void kernel_launch(void* const* d_in, const int* in_sizes, int n_in,
                              void* d_out, int out_size) {
    const float* x  = (const float*)d_in[0];
    const float* w1 = (const float*)d_in[1];
    const float* w2 = (const float*)d_in[2];
    const float* w3 = (const float*)d_in[3];
    const float* w4 = (const float*)d_in[4];
    float* out = (float*)d_out;

    float *a1, *a2, *a3;
    cudaGetSymbolAddress((void**)&a1, g_a1);
    cudaGetSymbolAddress((void**)&a2, g_a2);
    cudaGetSymbolAddress((void**)&a3, g_a3);

    const int smem1 = 784 * 18 * 4 + 144 * 4;   // 57024 B
    cudaFuncSetAttribute(k_layer1, cudaFuncAttributeMaxDynamicSharedMemorySize,
                         smem1);

    k_layer1<<<B / 16, 256, smem1>>>(x, w1, a1);
    k_layer2<<<dim3(64, 7, 2), 224>>>(a1, w2, a2);
    k_layer3<<<dim3(64, 4, 2), 128>>>(a2, w3, a3);
    k_layer4<<<B / 16, 512>>>(a3, w4, out);
}